// round 1
// baseline (speedup 1.0000x reference)
#include <cuda_runtime.h>
#include <math.h>

#define PB 8
#define NNODES_PER_B 2048
#define DD 128
#define HH 256
#define NODES (PB * NNODES_PER_B)   // 16384
#define TABP 4096
#define TABR 16.0f

// ---------------- device scratch (no allocations allowed) ----------------
__device__ float g_table[TABP * DD];   // 2 MB: filter(dist) lookup table
__device__ float g_sums[NODES * DD];   // 8 MB: scatter-sum accumulator
__device__ float g_cnt[NODES];         // edge counts per destination node
__device__ int   g_oddOr;              // int64-vs-int32 edge index detection

// ---------------- kernel 1: zero scratch ----------------
__global__ void zero_kernel() {
    int idx = blockIdx.x * blockDim.x + threadIdx.x;
    int stride = gridDim.x * blockDim.x;
    float4 z = make_float4(0.f, 0.f, 0.f, 0.f);
    const int n4 = (NODES * DD) / 4;
    for (int i = idx; i < n4; i += stride) ((float4*)g_sums)[i] = z;
    const int c4 = NODES / 4;
    for (int i = idx; i < c4; i += stride) ((float4*)g_cnt)[i] = z;
    if (idx == 0) g_oddOr = 0;
}

// ---------------- kernel 2: detect edge index dtype ----------------
// If indices are int64 (values < 2^31, nonnegative), every odd 32-bit word of
// the buffer is zero. If int32, odd words are random node indices -> OR != 0.
__global__ void detect_kernel(const int* __restrict__ p) {
    int acc = 0;
    for (int k = threadIdx.x; k < 2048; k += blockDim.x)
        acc |= p[2 * k + 1];
    if (acc) atomicOr(&g_oddOr, acc);
}

// ---------------- kernel 3: build filter table ----------------
// table[i, :] = silu(t_i * W1 + b1) @ W2 + b2,  t_i = i * (TABR/(TABP-1))
// One block = 32 table points, 128 threads (thread = output dim d).
__global__ void table_kernel(const float* __restrict__ W1, const float* __restrict__ b1,
                             const float* __restrict__ W2, const float* __restrict__ b2) {
    __shared__ float s[32 * 256];   // layout s[j*32 + p]  (j = hidden, p = point)
    const int tid = threadIdx.x;
    const int pBase = blockIdx.x * 32;
    const float delta = TABR / (float)(TABP - 1);

    for (int idx = tid; idx < 32 * 256; idx += 128) {
        int j = idx >> 5, p = idx & 31;
        float t = (float)(pBase + p) * delta;
        float a = t * W1[j] + b1[j];
        s[idx] = a / (1.0f + __expf(-a));     // silu
    }
    __syncthreads();

    const int d = tid;   // 0..127
    float acc[32];
#pragma unroll
    for (int p = 0; p < 32; p++) acc[p] = 0.f;

    for (int j = 0; j < 256; j++) {
        float w = W2[j * DD + d];
        const float4* sp = (const float4*)(s + j * 32);
#pragma unroll
        for (int q = 0; q < 8; q++) {
            float4 sv = sp[q];
            acc[4 * q + 0] += sv.x * w;
            acc[4 * q + 1] += sv.y * w;
            acc[4 * q + 2] += sv.z * w;
            acc[4 * q + 3] += sv.w * w;
        }
    }
    float bb = b2[d];
#pragma unroll
    for (int p = 0; p < 32; p++)
        g_table[(size_t)(pBase + p) * DD + d] = acc[p] + bb;
}

// ---------------- kernel 4: edge gather + interp + scatter ----------------
// One warp per edge; lane covers 4 feature dims (float4).
__global__ void edge_kernel(const float* __restrict__ x, const float* __restrict__ h,
                            const void* __restrict__ eiv, int E) {
    int g = blockIdx.x * blockDim.x + threadIdx.x;
    int e = g >> 5;
    int lane = threadIdx.x & 31;
    if (e >= E) return;

    int row, col;
    if (g_oddOr == 0) {  // int64 indices
        const long long* p = (const long long*)eiv;
        row = (int)p[e];
        col = (int)p[E + e];
    } else {             // int32 indices
        const int* p = (const int*)eiv;
        row = p[e];
        col = p[E + e];
    }

    float dx = x[row * 3 + 0] - x[col * 3 + 0];
    float dy = x[row * 3 + 1] - x[col * 3 + 1];
    float dz = x[row * 3 + 2] - x[col * 3 + 2];
    float dist = sqrtf(dx * dx + dy * dy + dz * dz);

    float t = dist * ((float)(TABP - 1) / TABR);
    int i0 = (int)t;
    if (i0 > TABP - 2) i0 = TABP - 2;
    float fr = t - (float)i0;

    const float4* tp = (const float4*)(g_table + (size_t)i0 * DD);
    float4 f0 = tp[lane];
    float4 f1 = tp[lane + 32];   // next table row (+128 floats = +32 float4)
    float4 hv = ((const float4*)(h + (size_t)col * DD))[lane];

    float m0 = hv.x * (f0.x + fr * (f1.x - f0.x));
    float m1 = hv.y * (f0.y + fr * (f1.y - f0.y));
    float m2 = hv.z * (f0.z + fr * (f1.z - f0.z));
    float m3 = hv.w * (f0.w + fr * (f1.w - f0.w));

    float* dst = g_sums + (size_t)row * DD + lane * 4;
    atomicAdd(dst + 0, m0);
    atomicAdd(dst + 1, m1);
    atomicAdd(dst + 2, m2);
    atomicAdd(dst + 3, m3);
    if (lane == 0) atomicAdd(&g_cnt[row], 1.0f);
}

// ---------------- kernel 5: fused node update MLP ----------------
// Block = 256 threads, 64 rows. A = [h | agg] (64x256) in smem.
// GEMM1 (x@W3+b3) -> LayerNorm -> SiLU -> GEMM2 (@W4+b4).
// Thread layout: warp = row group (8 rows), lane+32j = column.
__global__ void __launch_bounds__(256)
node_kernel(const float* __restrict__ h,
            const float* __restrict__ W3, const float* __restrict__ b3,
            const float* __restrict__ gamma, const float* __restrict__ beta,
            const float* __restrict__ W4, const float* __restrict__ b4,
            float* __restrict__ out) {
    extern __shared__ float sm[];
    float* As = sm;                 // 64*256 floats (64 KB)
    float* Ws = sm + 64 * 256;      // 8192 floats  (32 KB) weight chunk

    const int tid = threadIdx.x;
    const int lane = tid & 31;
    const int warp = tid >> 5;      // 0..7
    const int rowBase = blockIdx.x * 64;

    // ---- stage A: load [h | agg] tile ----
    for (int idx = tid; idx < 64 * 256; idx += 256) {
        int r = idx >> 8, c = idx & 255;
        int node = rowBase + r;
        float v;
        if (c < 128) {
            v = h[(size_t)node * DD + c];
        } else {
            float cn = g_cnt[node];
            v = g_sums[(size_t)node * DD + (c - 128)] / fmaxf(cn, 1.0f);
        }
        As[idx] = v;
    }
    __syncthreads();

    // ---- GEMM1: u = A(64x256) @ W3(256x256) ----
    float acc[8][8];
#pragma unroll
    for (int i = 0; i < 8; i++)
#pragma unroll
        for (int j = 0; j < 8; j++) acc[i][j] = 0.f;

    for (int kc = 0; kc < 256; kc += 32) {
        for (int idx = tid; idx < 32 * 256; idx += 256)
            Ws[idx] = W3[kc * 256 + idx];
        __syncthreads();
#pragma unroll 4
        for (int k = 0; k < 32; k++) {
            float a[8], w[8];
#pragma unroll
            for (int i = 0; i < 8; i++) a[i] = As[(warp * 8 + i) * 256 + kc + k];
#pragma unroll
            for (int j = 0; j < 8; j++) w[j] = Ws[k * 256 + lane + 32 * j];
#pragma unroll
            for (int i = 0; i < 8; i++)
#pragma unroll
                for (int j = 0; j < 8; j++) acc[i][j] += a[i] * w[j];
        }
        __syncthreads();
    }

    // ---- bias + LayerNorm + SiLU, store normalized activations into As ----
    float b3v[8], gav[8], bev[8];
#pragma unroll
    for (int j = 0; j < 8; j++) {
        int c = lane + 32 * j;
        b3v[j] = b3[c];
        gav[j] = gamma[c];
        bev[j] = beta[c];
    }
#pragma unroll
    for (int i = 0; i < 8; i++) {
        float s1 = 0.f, s2 = 0.f;
#pragma unroll
        for (int j = 0; j < 8; j++) {
            float u = acc[i][j] + b3v[j];
            acc[i][j] = u;
            s1 += u;
            s2 += u * u;
        }
#pragma unroll
        for (int off = 16; off > 0; off >>= 1) {
            s1 += __shfl_xor_sync(0xffffffffu, s1, off);
            s2 += __shfl_xor_sync(0xffffffffu, s2, off);
        }
        float mu = s1 * (1.0f / 256.0f);
        float var = s2 * (1.0f / 256.0f) - mu * mu;
        float rs = rsqrtf(var + 1e-5f);
#pragma unroll
        for (int j = 0; j < 8; j++) {
            float v = (acc[i][j] - mu) * rs * gav[j] + bev[j];
            float sv = v / (1.0f + __expf(-v));   // silu
            As[(warp * 8 + i) * 256 + lane + 32 * j] = sv;
        }
    }

    // ---- GEMM2: out = silu_u(64x256) @ W4(256x128) + b4 ----
    float acc2[8][4];
#pragma unroll
    for (int i = 0; i < 8; i++)
#pragma unroll
        for (int j = 0; j < 4; j++) acc2[i][j] = 0.f;

    for (int kc = 0; kc < 256; kc += 64) {
        for (int idx = tid; idx < 64 * 128; idx += 256)
            Ws[idx] = W4[kc * 128 + idx];
        __syncthreads();
#pragma unroll 4
        for (int k = 0; k < 64; k++) {
            float a[8], w[4];
#pragma unroll
            for (int i = 0; i < 8; i++) a[i] = As[(warp * 8 + i) * 256 + kc + k];
#pragma unroll
            for (int j = 0; j < 4; j++) w[j] = Ws[k * 128 + lane + 32 * j];
#pragma unroll
            for (int i = 0; i < 8; i++)
#pragma unroll
                for (int j = 0; j < 4; j++) acc2[i][j] += a[i] * w[j];
        }
        __syncthreads();
    }

    float b4v[4];
#pragma unroll
    for (int j = 0; j < 4; j++) b4v[j] = b4[lane + 32 * j];
#pragma unroll
    for (int i = 0; i < 8; i++) {
        int node = rowBase + warp * 8 + i;
#pragma unroll
        for (int j = 0; j < 4; j++)
            out[(size_t)node * DD + lane + 32 * j] = acc2[i][j] + b4v[j];
    }
}

// ---------------- host launcher ----------------
extern "C" void kernel_launch(void* const* d_in, const int* in_sizes, int n_in,
                              void* d_out, int out_size) {
    const float* x = (const float*)d_in[0];
    const float* h = (const float*)d_in[1];
    const void* ei = d_in[2];
    // batch_size may or may not be passed as a 1-element buffer
    int base = (in_sizes[3] == 1) ? 4 : 3;
    const float* W1 = (const float*)d_in[base + 0];
    const float* b1 = (const float*)d_in[base + 1];
    const float* W2 = (const float*)d_in[base + 2];
    const float* b2 = (const float*)d_in[base + 3];
    const float* W3 = (const float*)d_in[base + 4];
    const float* b3 = (const float*)d_in[base + 5];
    const float* ga = (const float*)d_in[base + 6];
    const float* be = (const float*)d_in[base + 7];
    const float* W4 = (const float*)d_in[base + 8];
    const float* b4 = (const float*)d_in[base + 9];
    float* out = (float*)d_out;

    const int E = in_sizes[2] / 2;

    zero_kernel<<<512, 256>>>();
    detect_kernel<<<1, 256>>>((const int*)ei);
    table_kernel<<<TABP / 32, 128>>>(W1, b1, W2, b2);

    int edge_blocks = (E * 32 + 255) / 256;
    edge_kernel<<<edge_blocks, 256>>>(x, h, ei, E);

    cudaFuncSetAttribute(node_kernel, cudaFuncAttributeMaxDynamicSharedMemorySize, 98304);
    node_kernel<<<NODES / 64, 256, 98304>>>(h, W3, b3, ga, be, W4, b4, out);

    (void)n_in; (void)out_size;
}

// round 2
// speedup vs baseline: 1.3615x; 1.3615x over previous
#include <cuda_runtime.h>
#include <math.h>

#define PB 8
#define NNODES_PER_B 2048
#define DD 128
#define HH 256
#define NODES (PB * NNODES_PER_B)   // 16384
#define TABP 4096
#define TABR 16.0f

// ---------------- device scratch (no allocations allowed) ----------------
__device__ float g_table[TABP * DD];   // 2 MB: filter(dist) lookup table
__device__ float g_sums[NODES * DD];   // 8 MB: scatter-sum accumulator
__device__ float g_cnt[NODES];         // edge counts per destination node
__device__ int   g_oddOr;              // int64-vs-int32 edge index detection

// ---------------- kernel 1: zero scratch ----------------
__global__ void zero_kernel() {
    int idx = blockIdx.x * blockDim.x + threadIdx.x;
    int stride = gridDim.x * blockDim.x;
    float4 z = make_float4(0.f, 0.f, 0.f, 0.f);
    const int n4 = (NODES * DD) / 4;
    for (int i = idx; i < n4; i += stride) ((float4*)g_sums)[i] = z;
    const int c4 = NODES / 4;
    for (int i = idx; i < c4; i += stride) ((float4*)g_cnt)[i] = z;
    if (idx == 0) g_oddOr = 0;
}

// ---------------- kernel 2: detect edge index dtype ----------------
__global__ void detect_kernel(const int* __restrict__ p) {
    int acc = 0;
    for (int k = threadIdx.x; k < 2048; k += blockDim.x)
        acc |= p[2 * k + 1];
    if (acc) atomicOr(&g_oddOr, acc);
}

// ---------------- kernel 3: build filter table ----------------
__global__ void table_kernel(const float* __restrict__ W1, const float* __restrict__ b1,
                             const float* __restrict__ W2, const float* __restrict__ b2) {
    __shared__ float s[32 * 256];   // s[j*32 + p]  (j = hidden, p = point)
    const int tid = threadIdx.x;
    const int pBase = blockIdx.x * 32;
    const float delta = TABR / (float)(TABP - 1);

    for (int idx = tid; idx < 32 * 256; idx += 128) {
        int j = idx >> 5, p = idx & 31;
        float t = (float)(pBase + p) * delta;
        float a = t * W1[j] + b1[j];
        s[idx] = a / (1.0f + __expf(-a));     // silu
    }
    __syncthreads();

    const int d = tid;   // 0..127
    float acc[32];
#pragma unroll
    for (int p = 0; p < 32; p++) acc[p] = 0.f;

    for (int j = 0; j < 256; j++) {
        float w = W2[j * DD + d];
        const float4* sp = (const float4*)(s + j * 32);
#pragma unroll
        for (int q = 0; q < 8; q++) {
            float4 sv = sp[q];
            acc[4 * q + 0] += sv.x * w;
            acc[4 * q + 1] += sv.y * w;
            acc[4 * q + 2] += sv.z * w;
            acc[4 * q + 3] += sv.w * w;
        }
    }
    float bb = b2[d];
#pragma unroll
    for (int p = 0; p < 32; p++)
        g_table[(size_t)(pBase + p) * DD + d] = acc[p] + bb;
}

// ---------------- kernel 4: edge gather + interp + scatter ----------------
// One warp per edge; lane covers 4 feature dims (float4).
// Scatter uses red.global.add.v4.f32 -> dense 512B atomic footprint per warp.
__global__ void edge_kernel(const float* __restrict__ x, const float* __restrict__ h,
                            const void* __restrict__ eiv, int E) {
    int g = blockIdx.x * blockDim.x + threadIdx.x;
    int e = g >> 5;
    int lane = threadIdx.x & 31;
    if (e >= E) return;

    int row, col;
    if (g_oddOr == 0) {  // int64 indices
        const long long* p = (const long long*)eiv;
        row = (int)p[e];
        col = (int)p[E + e];
    } else {             // int32 indices
        const int* p = (const int*)eiv;
        row = p[e];
        col = p[E + e];
    }

    float dx = x[row * 3 + 0] - x[col * 3 + 0];
    float dy = x[row * 3 + 1] - x[col * 3 + 1];
    float dz = x[row * 3 + 2] - x[col * 3 + 2];
    float dist = sqrtf(dx * dx + dy * dy + dz * dz);

    float t = dist * ((float)(TABP - 1) / TABR);
    int i0 = (int)t;
    if (i0 > TABP - 2) i0 = TABP - 2;
    float fr = t - (float)i0;

    const float4* tp = (const float4*)(g_table + (size_t)i0 * DD);
    float4 f0 = tp[lane];
    float4 f1 = tp[lane + 32];   // next table row
    float4 hv = ((const float4*)(h + (size_t)col * DD))[lane];

    float m0 = hv.x * (f0.x + fr * (f1.x - f0.x));
    float m1 = hv.y * (f0.y + fr * (f1.y - f0.y));
    float m2 = hv.z * (f0.z + fr * (f1.z - f0.z));
    float m3 = hv.w * (f0.w + fr * (f1.w - f0.w));

    float* dst = g_sums + (size_t)row * DD + lane * 4;
    asm volatile("red.global.add.v4.f32 [%0], {%1, %2, %3, %4};"
                 :: "l"(dst), "f"(m0), "f"(m1), "f"(m2), "f"(m3) : "memory");
    if (lane == 0) {
        asm volatile("red.global.add.f32 [%0], %1;"
                     :: "l"(&g_cnt[row]), "f"(1.0f) : "memory");
    }
}

// ---------------- kernel 5: fused node update MLP ----------------
__global__ void __launch_bounds__(256)
node_kernel(const float* __restrict__ h,
            const float* __restrict__ W3, const float* __restrict__ b3,
            const float* __restrict__ gamma, const float* __restrict__ beta,
            const float* __restrict__ W4, const float* __restrict__ b4,
            float* __restrict__ out) {
    extern __shared__ float sm[];
    float* As = sm;                 // 64*256 floats (64 KB)
    float* Ws = sm + 64 * 256;      // 8192 floats  (32 KB) weight chunk

    const int tid = threadIdx.x;
    const int lane = tid & 31;
    const int warp = tid >> 5;      // 0..7
    const int rowBase = blockIdx.x * 64;

    // ---- stage A: load [h | agg] tile ----
    for (int idx = tid; idx < 64 * 256; idx += 256) {
        int r = idx >> 8, c = idx & 255;
        int node = rowBase + r;
        float v;
        if (c < 128) {
            v = h[(size_t)node * DD + c];
        } else {
            float cn = g_cnt[node];
            v = g_sums[(size_t)node * DD + (c - 128)] / fmaxf(cn, 1.0f);
        }
        As[idx] = v;
    }
    __syncthreads();

    // ---- GEMM1: u = A(64x256) @ W3(256x256) ----
    float acc[8][8];
#pragma unroll
    for (int i = 0; i < 8; i++)
#pragma unroll
        for (int j = 0; j < 8; j++) acc[i][j] = 0.f;

    for (int kc = 0; kc < 256; kc += 32) {
        for (int idx = tid; idx < 32 * 256; idx += 256)
            Ws[idx] = W3[kc * 256 + idx];
        __syncthreads();
#pragma unroll 4
        for (int k = 0; k < 32; k++) {
            float a[8], w[8];
#pragma unroll
            for (int i = 0; i < 8; i++) a[i] = As[(warp * 8 + i) * 256 + kc + k];
#pragma unroll
            for (int j = 0; j < 8; j++) w[j] = Ws[k * 256 + lane + 32 * j];
#pragma unroll
            for (int i = 0; i < 8; i++)
#pragma unroll
                for (int j = 0; j < 8; j++) acc[i][j] += a[i] * w[j];
        }
        __syncthreads();
    }

    // ---- bias + LayerNorm + SiLU ----
    float b3v[8], gav[8], bev[8];
#pragma unroll
    for (int j = 0; j < 8; j++) {
        int c = lane + 32 * j;
        b3v[j] = b3[c];
        gav[j] = gamma[c];
        bev[j] = beta[c];
    }
#pragma unroll
    for (int i = 0; i < 8; i++) {
        float s1 = 0.f, s2 = 0.f;
#pragma unroll
        for (int j = 0; j < 8; j++) {
            float u = acc[i][j] + b3v[j];
            acc[i][j] = u;
            s1 += u;
            s2 += u * u;
        }
#pragma unroll
        for (int off = 16; off > 0; off >>= 1) {
            s1 += __shfl_xor_sync(0xffffffffu, s1, off);
            s2 += __shfl_xor_sync(0xffffffffu, s2, off);
        }
        float mu = s1 * (1.0f / 256.0f);
        float var = s2 * (1.0f / 256.0f) - mu * mu;
        float rs = rsqrtf(var + 1e-5f);
#pragma unroll
        for (int j = 0; j < 8; j++) {
            float v = (acc[i][j] - mu) * rs * gav[j] + bev[j];
            float sv = v / (1.0f + __expf(-v));   // silu
            As[(warp * 8 + i) * 256 + lane + 32 * j] = sv;
        }
    }

    // ---- GEMM2: out = silu_u(64x256) @ W4(256x128) + b4 ----
    float acc2[8][4];
#pragma unroll
    for (int i = 0; i < 8; i++)
#pragma unroll
        for (int j = 0; j < 4; j++) acc2[i][j] = 0.f;

    for (int kc = 0; kc < 256; kc += 64) {
        for (int idx = tid; idx < 64 * 128; idx += 256)
            Ws[idx] = W4[kc * 128 + idx];
        __syncthreads();
#pragma unroll 4
        for (int k = 0; k < 64; k++) {
            float a[8], w[4];
#pragma unroll
            for (int i = 0; i < 8; i++) a[i] = As[(warp * 8 + i) * 256 + kc + k];
#pragma unroll
            for (int j = 0; j < 4; j++) w[j] = Ws[k * 128 + lane + 32 * j];
#pragma unroll
            for (int i = 0; i < 8; i++)
#pragma unroll
                for (int j = 0; j < 4; j++) acc2[i][j] += a[i] * w[j];
        }
        __syncthreads();
    }

    float b4v[4];
#pragma unroll
    for (int j = 0; j < 4; j++) b4v[j] = b4[lane + 32 * j];
#pragma unroll
    for (int i = 0; i < 8; i++) {
        int node = rowBase + warp * 8 + i;
#pragma unroll
        for (int j = 0; j < 4; j++)
            out[(size_t)node * DD + lane + 32 * j] = acc2[i][j] + b4v[j];
    }
}

// ---------------- host launcher ----------------
extern "C" void kernel_launch(void* const* d_in, const int* in_sizes, int n_in,
                              void* d_out, int out_size) {
    const float* x = (const float*)d_in[0];
    const float* h = (const float*)d_in[1];
    const void* ei = d_in[2];
    int base = (in_sizes[3] == 1) ? 4 : 3;
    const float* W1 = (const float*)d_in[base + 0];
    const float* b1 = (const float*)d_in[base + 1];
    const float* W2 = (const float*)d_in[base + 2];
    const float* b2 = (const float*)d_in[base + 3];
    const float* W3 = (const float*)d_in[base + 4];
    const float* b3 = (const float*)d_in[base + 5];
    const float* ga = (const float*)d_in[base + 6];
    const float* be = (const float*)d_in[base + 7];
    const float* W4 = (const float*)d_in[base + 8];
    const float* b4 = (const float*)d_in[base + 9];
    float* out = (float*)d_out;

    const int E = in_sizes[2] / 2;

    zero_kernel<<<512, 256>>>();
    detect_kernel<<<1, 256>>>((const int*)ei);
    table_kernel<<<TABP / 32, 128>>>(W1, b1, W2, b2);

    int edge_blocks = (E * 32 + 255) / 256;
    edge_kernel<<<edge_blocks, 256>>>(x, h, ei, E);

    cudaFuncSetAttribute(node_kernel, cudaFuncAttributeMaxDynamicSharedMemorySize, 98304);
    node_kernel<<<NODES / 64, 256, 98304>>>(h, W3, b3, ga, be, W4, b4, out);

    (void)n_in; (void)out_size;
}

// round 4
// speedup vs baseline: 1.7953x; 1.3186x over previous
#include <cuda_runtime.h>
#include <cuda_bf16.h>
#include <math.h>
#include <cstdint>

#define PB 8
#define NNODES_PER_B 2048
#define DD 128
#define HH 256
#define NODES (PB * NNODES_PER_B)   // 16384
#define TABP 4096
#define TABR 16.0f

// ---------------- device scratch ----------------
__device__ float g_table[TABP * DD];   // 2 MB filter table
__device__ float g_sums[NODES * DD];   // 8 MB scatter-sum
__device__ float g_cnt[NODES];
__device__ int   g_oddOr;
// split weights (transposed to [N][K], bf16 hi/lo), 16B-aligned for uint4 loads
__device__ __align__(16) __nv_bfloat16 g_w3h[256 * 256];
__device__ __align__(16) __nv_bfloat16 g_w3l[256 * 256];
__device__ __align__(16) __nv_bfloat16 g_w4h[128 * 256];
__device__ __align__(16) __nv_bfloat16 g_w4l[128 * 256];

// ---------------- kernel 1: zero scratch ----------------
__global__ void zero_kernel() {
    int idx = blockIdx.x * blockDim.x + threadIdx.x;
    int stride = gridDim.x * blockDim.x;
    float4 z = make_float4(0.f, 0.f, 0.f, 0.f);
    const int n4 = (NODES * DD) / 4;
    for (int i = idx; i < n4; i += stride) ((float4*)g_sums)[i] = z;
    const int c4 = NODES / 4;
    for (int i = idx; i < c4; i += stride) ((float4*)g_cnt)[i] = z;
    if (idx == 0) g_oddOr = 0;
}

// ---------------- kernel 2: detect edge index dtype ----------------
__global__ void detect_kernel(const int* __restrict__ p) {
    int acc = 0;
    for (int k = threadIdx.x; k < 2048; k += blockDim.x) acc |= p[2 * k + 1];
    if (acc) atomicOr(&g_oddOr, acc);
}

// ---------------- kernel 3: build filter table ----------------
__global__ void table_kernel(const float* __restrict__ W1, const float* __restrict__ b1,
                             const float* __restrict__ W2, const float* __restrict__ b2) {
    __shared__ float s[32 * 256];
    const int tid = threadIdx.x;
    const int pBase = blockIdx.x * 32;
    const float delta = TABR / (float)(TABP - 1);
    for (int idx = tid; idx < 32 * 256; idx += 128) {
        int j = idx >> 5, p = idx & 31;
        float t = (float)(pBase + p) * delta;
        float a = t * W1[j] + b1[j];
        s[idx] = a / (1.0f + __expf(-a));
    }
    __syncthreads();
    const int d = tid;
    float acc[32];
#pragma unroll
    for (int p = 0; p < 32; p++) acc[p] = 0.f;
    for (int j = 0; j < 256; j++) {
        float w = W2[j * DD + d];
        const float4* sp = (const float4*)(s + j * 32);
#pragma unroll
        for (int q = 0; q < 8; q++) {
            float4 sv = sp[q];
            acc[4 * q + 0] += sv.x * w; acc[4 * q + 1] += sv.y * w;
            acc[4 * q + 2] += sv.z * w; acc[4 * q + 3] += sv.w * w;
        }
    }
    float bb = b2[d];
#pragma unroll
    for (int p = 0; p < 32; p++)
        g_table[(size_t)(pBase + p) * DD + d] = acc[p] + bb;
}

// ---------------- kernel 3b: split weights to bf16 hi/lo (transposed) ----------------
__global__ void wsplit_kernel(const float* __restrict__ W3, const float* __restrict__ W4) {
    int idx = blockIdx.x * blockDim.x + threadIdx.x;
    if (idx < 256 * 256) {
        int n = idx >> 8, k = idx & 255;
        float v = W3[k * 256 + n];
        __nv_bfloat16 hi = __float2bfloat16_rn(v);
        g_w3h[idx] = hi;
        g_w3l[idx] = __float2bfloat16_rn(v - __bfloat162float(hi));
    } else if (idx < 256 * 256 + 128 * 256) {
        int j = idx - 256 * 256;
        int n = j >> 8, k = j & 255;
        float v = W4[k * 128 + n];
        __nv_bfloat16 hi = __float2bfloat16_rn(v);
        g_w4h[j] = hi;
        g_w4l[j] = __float2bfloat16_rn(v - __bfloat162float(hi));
    }
}

// ---------------- kernel 4: edge gather + interp + scatter ----------------
__global__ void edge_kernel(const float* __restrict__ x, const float* __restrict__ h,
                            const void* __restrict__ eiv, int E) {
    int g = blockIdx.x * blockDim.x + threadIdx.x;
    int e = g >> 5;
    int lane = threadIdx.x & 31;
    if (e >= E) return;
    int row, col;
    if (g_oddOr == 0) {
        const long long* p = (const long long*)eiv;
        row = (int)p[e]; col = (int)p[E + e];
    } else {
        const int* p = (const int*)eiv;
        row = p[e]; col = p[E + e];
    }
    float dx = x[row * 3 + 0] - x[col * 3 + 0];
    float dy = x[row * 3 + 1] - x[col * 3 + 1];
    float dz = x[row * 3 + 2] - x[col * 3 + 2];
    float dist = sqrtf(dx * dx + dy * dy + dz * dz);
    float t = dist * ((float)(TABP - 1) / TABR);
    int i0 = (int)t;
    if (i0 > TABP - 2) i0 = TABP - 2;
    float fr = t - (float)i0;
    const float4* tp = (const float4*)(g_table + (size_t)i0 * DD);
    float4 f0 = tp[lane];
    float4 f1 = tp[lane + 32];
    float4 hv = ((const float4*)(h + (size_t)col * DD))[lane];
    float m0 = hv.x * (f0.x + fr * (f1.x - f0.x));
    float m1 = hv.y * (f0.y + fr * (f1.y - f0.y));
    float m2 = hv.z * (f0.z + fr * (f1.z - f0.z));
    float m3 = hv.w * (f0.w + fr * (f1.w - f0.w));
    float* dst = g_sums + (size_t)row * DD + lane * 4;
    asm volatile("red.global.add.v4.f32 [%0], {%1, %2, %3, %4};"
                 :: "l"(dst), "f"(m0), "f"(m1), "f"(m2), "f"(m3) : "memory");
    if (lane == 0)
        asm volatile("red.global.add.f32 [%0], %1;" :: "l"(&g_cnt[row]), "f"(1.0f) : "memory");
}

// ---------------- kernel 5: mma.sync bf16 fused node MLP ----------------
// smem (bytes): A_hi [128][264 bf16 padded] 67584 | A_lo 67584 | B 67584 | params
#define PADW 132                       // u32 words per padded row (264 bf16)
#define OFF_ALO (128 * PADW)           // u32 offsets
#define OFF_B   (2 * 128 * PADW)
#define SM_U32  (3 * 128 * PADW)       // 50688 u32 = 202752 B
#define SMEM_NODE (202752 + 1024 * 3 + 512 + 1024 * 2)   // + b3,ga,be,b4,s1,s2 = 208384

__device__ __forceinline__ void mma_bf16(float* c, const uint32_t* a, uint32_t b0, uint32_t b1) {
    asm volatile("mma.sync.aligned.m16n8k16.row.col.f32.bf16.bf16.f32 "
                 "{%0,%1,%2,%3}, {%4,%5,%6,%7}, {%8,%9}, {%0,%1,%2,%3};"
                 : "+f"(c[0]), "+f"(c[1]), "+f"(c[2]), "+f"(c[3])
                 : "r"(a[0]), "r"(a[1]), "r"(a[2]), "r"(a[3]), "r"(b0), "r"(b1));
}

__device__ __forceinline__ uint32_t pack_split(float v0, float v1, uint32_t& lo) {
    __nv_bfloat16 h0 = __float2bfloat16_rn(v0);
    __nv_bfloat16 h1 = __float2bfloat16_rn(v1);
    __nv_bfloat16 l0 = __float2bfloat16_rn(v0 - __bfloat162float(h0));
    __nv_bfloat16 l1 = __float2bfloat16_rn(v1 - __bfloat162float(h1));
    lo = ((uint32_t)__bfloat16_as_ushort(l1) << 16) | __bfloat16_as_ushort(l0);
    return ((uint32_t)__bfloat16_as_ushort(h1) << 16) | __bfloat16_as_ushort(h0);
}

// one K=256 pass: C[warp 32x64] += A_sel @ B_chunk^T, acc tiles [mt][NTBASE+nt]
template <int NTBASE>
__device__ __forceinline__ void gemm_pass(const uint32_t* __restrict__ Asm,
                                          const uint32_t* __restrict__ Bsm,
                                          float (&acc)[2][16][4],
                                          int mr, int nwBase, int g, int tg) {
    for (int ks = 0; ks < 16; ks++) {
        uint32_t a[2][4];
#pragma unroll
        for (int mt = 0; mt < 2; mt++) {
            int w = (mr + mt * 16 + g) * PADW + ks * 8 + tg;
            a[mt][0] = Asm[w];
            a[mt][1] = Asm[w + 8 * PADW];
            a[mt][2] = Asm[w + 4];
            a[mt][3] = Asm[w + 8 * PADW + 4];
        }
#pragma unroll
        for (int nt = 0; nt < 8; nt++) {
            int bw = (nwBase + nt * 8 + g) * PADW + ks * 8 + tg;
            uint32_t b0 = Bsm[bw], b1 = Bsm[bw + 4];
            mma_bf16(acc[0][NTBASE + nt], a[0], b0, b1);
            mma_bf16(acc[1][NTBASE + nt], a[1], b0, b1);
        }
    }
}

__device__ __forceinline__ void load_b128(uint4* __restrict__ dstB,
                                          const uint4* __restrict__ src, int nOff) {
    for (int i = threadIdx.x; i < 128 * 32; i += 256) {
        int nl = i >> 5, k4 = i & 31;
        dstB[nl * 33 + k4] = src[(nOff + nl) * 32 + k4];
    }
}

__global__ void __launch_bounds__(256, 1)
node_kernel(const float* __restrict__ h,
            const float* __restrict__ b3, const float* __restrict__ gamma,
            const float* __restrict__ beta, const float* __restrict__ b4,
            float* __restrict__ out) {
    extern __shared__ uint32_t sm[];
    uint32_t* Ahi = sm;
    uint32_t* Alo = sm + OFF_ALO;
    uint32_t* Bsm = sm + OFF_B;
    float* sm_b3 = (float*)(sm + SM_U32);
    float* sm_ga = sm_b3 + 256;
    float* sm_be = sm_ga + 256;
    float* sm_b4 = sm_be + 256;
    float* sm_s1 = sm_b4 + 128;          // [128][2]
    float* sm_s2 = sm_s1 + 256;          // [128][2]

    const int tid = threadIdx.x;
    const int lane = tid & 31;
    const int wid = tid >> 5;            // 0..7
    const int g = lane >> 2;             // groupID
    const int tg = lane & 3;             // thread-in-group
    const int mw = wid & 3;              // warp m index (rows 32*mw)
    const int nw = wid >> 2;             // warp n index (cols 64*nw in chunk)
    const int mr = mw * 32;
    const int nwBase = nw * 64;
    const int rowBase = blockIdx.x * 128;

    // stage params
    sm_b3[tid] = b3[tid];
    sm_ga[tid] = gamma[tid];
    sm_be[tid] = beta[tid];
    if (tid < 128) sm_b4[tid] = b4[tid];

    // ---- build A = [h | agg], split hi/lo, padded rows ----
    for (int idx = tid; idx < 128 * 64; idx += 256) {
        int row = idx >> 6, kp = idx & 63;
        float2 v = ((const float2*)(h + (size_t)(rowBase + row) * DD))[kp];
        uint32_t lo, hi = pack_split(v.x, v.y, lo);
        Ahi[row * PADW + kp] = hi;
        Alo[row * PADW + kp] = lo;
    }
    for (int idx = tid; idx < 128 * 64; idx += 256) {
        int row = idx >> 6, kp = idx & 63;
        int node = rowBase + row;
        float inv = 1.0f / fmaxf(g_cnt[node], 1.0f);
        float2 v = ((const float2*)(g_sums + (size_t)node * DD))[kp];
        uint32_t lo, hi = pack_split(v.x * inv, v.y * inv, lo);
        Ahi[row * PADW + 64 + kp] = hi;
        Alo[row * PADW + 64 + kp] = lo;
    }

    float acc[2][16][4];
#pragma unroll
    for (int mt = 0; mt < 2; mt++)
#pragma unroll
        for (int nt = 0; nt < 16; nt++)
#pragma unroll
            for (int f = 0; f < 4; f++) acc[mt][nt][f] = 0.f;

    // ---- GEMM1: 2 chunks of 128 cols; 3-way split passes ----
#pragma unroll
    for (int chunk = 0; chunk < 2; chunk++) {
        __syncthreads();
        load_b128((uint4*)Bsm, (const uint4*)g_w3h, chunk * 128);
        __syncthreads();
        if (chunk == 0) {
            gemm_pass<0>(Ahi, Bsm, acc, mr, nwBase, g, tg);
            gemm_pass<0>(Alo, Bsm, acc, mr, nwBase, g, tg);
        } else {
            gemm_pass<8>(Ahi, Bsm, acc, mr, nwBase, g, tg);
            gemm_pass<8>(Alo, Bsm, acc, mr, nwBase, g, tg);
        }
        __syncthreads();
        load_b128((uint4*)Bsm, (const uint4*)g_w3l, chunk * 128);
        __syncthreads();
        if (chunk == 0) gemm_pass<0>(Ahi, Bsm, acc, mr, nwBase, g, tg);
        else            gemm_pass<8>(Ahi, Bsm, acc, mr, nwBase, g, tg);
    }
    __syncthreads();

    // ---- epilogue 1: +b3, LayerNorm, SiLU, re-split into A buffers ----
    // lane's 4 row slots: [0]=mr+g, [1]=mr+g+8, [2]=mr+16+g, [3]=mr+24+g
    float s1[4] = {0.f, 0.f, 0.f, 0.f}, s2[4] = {0.f, 0.f, 0.f, 0.f};
#pragma unroll
    for (int mt = 0; mt < 2; mt++)
#pragma unroll
        for (int q = 0; q < 16; q++) {
            int chunk = q >> 3, nt = q & 7;
            int c0 = chunk * 128 + nwBase + nt * 8 + 2 * tg;
            float u0 = acc[mt][q][0] + sm_b3[c0];
            float u1 = acc[mt][q][1] + sm_b3[c0 + 1];
            float u2 = acc[mt][q][2] + sm_b3[c0];
            float u3 = acc[mt][q][3] + sm_b3[c0 + 1];
            acc[mt][q][0] = u0; acc[mt][q][1] = u1;
            acc[mt][q][2] = u2; acc[mt][q][3] = u3;
            s1[mt * 2 + 0] += u0 + u1;  s2[mt * 2 + 0] += u0 * u0 + u1 * u1;
            s1[mt * 2 + 1] += u2 + u3;  s2[mt * 2 + 1] += u2 * u2 + u3 * u3;
        }
#pragma unroll
    for (int r = 0; r < 4; r++) {
#pragma unroll
        for (int off = 1; off < 4; off <<= 1) {
            s1[r] += __shfl_xor_sync(0xffffffffu, s1[r], off);
            s2[r] += __shfl_xor_sync(0xffffffffu, s2[r], off);
        }
    }
    if (tg == 0) {
        int rows[4] = {mr + g, mr + g + 8, mr + 16 + g, mr + 24 + g};
#pragma unroll
        for (int r = 0; r < 4; r++) {
            sm_s1[rows[r] * 2 + nw] = s1[r];
            sm_s2[rows[r] * 2 + nw] = s2[r];
        }
    }
    __syncthreads();
    float mu[4], rs[4];
    {
        int rows[4] = {mr + g, mr + g + 8, mr + 16 + g, mr + 24 + g};
#pragma unroll
        for (int r = 0; r < 4; r++) {
            float S1 = sm_s1[rows[r] * 2] + sm_s1[rows[r] * 2 + 1];
            float S2 = sm_s2[rows[r] * 2] + sm_s2[rows[r] * 2 + 1];
            float m = S1 * (1.0f / 256.0f);
            float var = S2 * (1.0f / 256.0f) - m * m;
            mu[r] = m;
            rs[r] = rsqrtf(var + 1e-5f);
        }
    }
    __syncthreads();   // GEMM1 done everywhere before overwriting A
#pragma unroll
    for (int mt = 0; mt < 2; mt++)
#pragma unroll
        for (int q = 0; q < 16; q++) {
            int chunk = q >> 3, nt = q & 7;
            int c0 = chunk * 128 + nwBase + nt * 8 + 2 * tg;
            float ga0 = sm_ga[c0], ga1 = sm_ga[c0 + 1];
            float be0 = sm_be[c0], be1 = sm_be[c0 + 1];
            int rlo = mr + mt * 16 + g;
            // row low (frags 0,1), slot mt*2
            {
                float v0 = (acc[mt][q][0] - mu[mt * 2]) * rs[mt * 2] * ga0 + be0;
                float v1 = (acc[mt][q][1] - mu[mt * 2]) * rs[mt * 2] * ga1 + be1;
                float w0 = v0 / (1.0f + __expf(-v0));
                float w1 = v1 / (1.0f + __expf(-v1));
                uint32_t lo, hi = pack_split(w0, w1, lo);
                int word = rlo * PADW + (c0 >> 1);
                Ahi[word] = hi; Alo[word] = lo;
            }
            // row high (frags 2,3), slot mt*2+1
            {
                float v0 = (acc[mt][q][2] - mu[mt * 2 + 1]) * rs[mt * 2 + 1] * ga0 + be0;
                float v1 = (acc[mt][q][3] - mu[mt * 2 + 1]) * rs[mt * 2 + 1] * ga1 + be1;
                float w0 = v0 / (1.0f + __expf(-v0));
                float w1 = v1 / (1.0f + __expf(-v1));
                uint32_t lo, hi = pack_split(w0, w1, lo);
                int word = (rlo + 8) * PADW + (c0 >> 1);
                Ahi[word] = hi; Alo[word] = lo;
            }
        }

    // ---- GEMM2: C2(128x128) = A2 @ W4T^T ----
#pragma unroll
    for (int mt = 0; mt < 2; mt++)
#pragma unroll
        for (int nt = 0; nt < 8; nt++)
#pragma unroll
            for (int f = 0; f < 4; f++) acc[mt][nt][f] = 0.f;

    __syncthreads();
    load_b128((uint4*)Bsm, (const uint4*)g_w4h, 0);
    __syncthreads();
    gemm_pass<0>(Ahi, Bsm, acc, mr, nwBase, g, tg);
    gemm_pass<0>(Alo, Bsm, acc, mr, nwBase, g, tg);
    __syncthreads();
    load_b128((uint4*)Bsm, (const uint4*)g_w4l, 0);
    __syncthreads();
    gemm_pass<0>(Ahi, Bsm, acc, mr, nwBase, g, tg);

    // ---- epilogue 2: +b4, store ----
#pragma unroll
    for (int mt = 0; mt < 2; mt++)
#pragma unroll
        for (int nt = 0; nt < 8; nt++) {
            int c0 = nwBase + nt * 8 + 2 * tg;
            float bb0 = sm_b4[c0], bb1 = sm_b4[c0 + 1];
            int rlo = rowBase + mr + mt * 16 + g;
            float2 v0 = make_float2(acc[mt][nt][0] + bb0, acc[mt][nt][1] + bb1);
            float2 v1 = make_float2(acc[mt][nt][2] + bb0, acc[mt][nt][3] + bb1);
            *(float2*)(out + (size_t)rlo * DD + c0) = v0;
            *(float2*)(out + (size_t)(rlo + 8) * DD + c0) = v1;
        }
}

// ---------------- host launcher ----------------
extern "C" void kernel_launch(void* const* d_in, const int* in_sizes, int n_in,
                              void* d_out, int out_size) {
    const float* x = (const float*)d_in[0];
    const float* h = (const float*)d_in[1];
    const void* ei = d_in[2];
    int base = (in_sizes[3] == 1) ? 4 : 3;
    const float* W1 = (const float*)d_in[base + 0];
    const float* b1 = (const float*)d_in[base + 1];
    const float* W2 = (const float*)d_in[base + 2];
    const float* b2 = (const float*)d_in[base + 3];
    const float* W3 = (const float*)d_in[base + 4];
    const float* b3 = (const float*)d_in[base + 5];
    const float* ga = (const float*)d_in[base + 6];
    const float* be = (const float*)d_in[base + 7];
    const float* W4 = (const float*)d_in[base + 8];
    const float* b4 = (const float*)d_in[base + 9];
    float* out = (float*)d_out;

    const int E = in_sizes[2] / 2;

    zero_kernel<<<512, 256>>>();
    detect_kernel<<<1, 256>>>((const int*)ei);
    table_kernel<<<TABP / 32, 128>>>(W1, b1, W2, b2);
    wsplit_kernel<<<(256 * 256 + 128 * 256 + 255) / 256, 256>>>(W3, W4);

    int edge_blocks = (E * 32 + 255) / 256;
    edge_kernel<<<edge_blocks, 256>>>(x, h, ei, E);

    cudaFuncSetAttribute(node_kernel, cudaFuncAttributeMaxDynamicSharedMemorySize, SMEM_NODE);
    node_kernel<<<NODES / 128, 256, SMEM_NODE>>>(h, b3, ga, be, b4, out);

    (void)n_in; (void)out_size;
}